// round 2
// baseline (speedup 1.0000x reference)
#include <cuda_runtime.h>
#include <math.h>
#include <float.h>

#define NB 8
#define NT 2048
#define ND 1024
#define NP 512
#define NS 256

// ---------------- scratch (static __device__ — no allocations) ----------------
__device__ float g_scores[NB*NT];
__device__ float g_sscore[NB*NT];
__device__ int   g_summap[NB*NP];
__device__ int   g_src[NB*NP];
__device__ int   g_counts[NB];
__device__ float g_summ[NB*NP*NS];
__device__ float g_poolf[NB*NP*NS];
__device__ float g_q[NB*NT*NS];
__device__ float g_k[NB*NP*NS];
__device__ float g_v[NB*NP*ND];

// =============================================================================
// Kernel 1: scores = sigmoid(relu(X @ w1) @ w2).  One block = 32 tokens.
// High-precision: fp32 FMA within 32-wide k-blocks, fp64 accumulation across
// blocks (stage 1); h rounded to fp32 (matches reference's fp32 relu input);
// stage 2 + reduction + sigmoid in fp64. Scores must be accurate to <<1e-7 so
// sorted-rank comparisons match the reference's fp32 values.
// =============================================================================
__global__ __launch_bounds__(256) void score_kernel(
    const float* __restrict__ tokens, const float* __restrict__ w1,
    const float* __restrict__ w2)
{
    __shared__ float xs[32][33];
    __shared__ float ws[32][257];
    __shared__ float w2s[256];
    int tid = threadIdx.x;
    int tx = tid & 63, ty = tid >> 6;
    int r0 = blockIdx.x * 32;
    w2s[tid] = w2[tid];

    double accd[8][4];
#pragma unroll
    for (int r = 0; r < 8; r++)
#pragma unroll
        for (int c = 0; c < 4; c++) accd[r][c] = 0.0;

    for (int k0 = 0; k0 < ND; k0 += 32) {
#pragma unroll
        for (int l = 0; l < 4; l++) {
            int idx = tid + l*256; int t = idx >> 5, kk = idx & 31;
            xs[t][kk] = tokens[(size_t)(r0 + t)*ND + k0 + kk];
        }
#pragma unroll
        for (int l = 0; l < 32; l++) {
            int idx = tid + l*256; int kk = idx >> 8, j = idx & 255;
            ws[kk][j] = w1[(size_t)(k0 + kk)*NS + j];
        }
        __syncthreads();
        float blk[8][4];
#pragma unroll
        for (int r = 0; r < 8; r++)
#pragma unroll
            for (int c = 0; c < 4; c++) blk[r][c] = 0.f;
#pragma unroll
        for (int kk = 0; kk < 32; kk++) {
            float bw[4], ax[8];
#pragma unroll
            for (int c = 0; c < 4; c++) bw[c] = ws[kk][tx + 64*c];
#pragma unroll
            for (int r = 0; r < 8; r++) ax[r] = xs[ty*8 + r][kk];
#pragma unroll
            for (int r = 0; r < 8; r++)
#pragma unroll
                for (int c = 0; c < 4; c++) blk[r][c] += ax[r]*bw[c];
        }
#pragma unroll
        for (int r = 0; r < 8; r++)
#pragma unroll
            for (int c = 0; c < 4; c++) accd[r][c] += (double)blk[r][c];
        __syncthreads();
    }
    // epilogue: round h to fp32, relu, weight by w2 (fp64), reduce (fp64)
    // reuse ws storage as a double scratch (32 rows x pitch 65 doubles = 16.6KB)
    double* red = (double*)&ws[0][0];
#pragma unroll
    for (int r = 0; r < 8; r++) {
        double p = 0.0;
#pragma unroll
        for (int c = 0; c < 4; c++) {
            float h = (float)accd[r][c];           // reference's fp32 h
            p += (double)fmaxf(h, 0.f) * (double)w2s[tx + 64*c];
        }
        red[(ty*8 + r)*65 + tx] = p;
    }
    __syncthreads();
    if (tid < 32) {
        double s = 0.0;
#pragma unroll 8
        for (int x = 0; x < 64; x++) s += red[tid*65 + x];
        g_scores[r0 + tid] = (float)(1.0 / (1.0 + exp(-s)));
    }
}

// =============================================================================
// Kernel 2: per-batch bitonic sort, descending score, ascending idx tiebreak
// (matches stable jnp.argsort(-scores)). Also builds summaries row map.
// =============================================================================
__global__ __launch_bounds__(1024) void sort_kernel()
{
    __shared__ float key[NT];
    __shared__ int   sidx[NT];
    int b = blockIdx.x, tid = threadIdx.x;
    for (int i = tid; i < NT; i += 1024) { key[i] = g_scores[b*NT + i]; sidx[i] = i; }
    __syncthreads();
    for (int k = 2; k <= NT; k <<= 1) {
        for (int j = k >> 1; j > 0; j >>= 1) {
#pragma unroll
            for (int l = 0; l < 2; l++) {
                int i = tid + l*1024;
                int ixj = i ^ j;
                if (ixj > i) {
                    bool up = ((i & k) == 0);
                    float ka = key[i], kb = key[ixj];
                    int ia = sidx[i], ib = sidx[ixj];
                    // gt: element i sorts AFTER ixj in final order (score desc, idx asc)
                    bool gt = (ka < kb) || (ka == kb && ia > ib);
                    if (gt == up) {
                        key[i] = kb; key[ixj] = ka;
                        sidx[i] = ib; sidx[ixj] = ia;
                    }
                }
            }
            __syncthreads();
        }
    }
    for (int i = tid; i < NT; i += 1024) g_sscore[b*NT + i] = key[i];
    if (tid < NP) g_summap[b*NP + tid] = b*NT + sidx[tid];
}

// =============================================================================
// Kernel 3 (generic fp32 GEMM): C[M,N] = A[rowmap(m), K] @ B[K, N]
// block = 32 rows x 256 cols; thread micro-tile 8x4.
// =============================================================================
__global__ __launch_bounds__(256) void gemm32x256(
    const float* __restrict__ A, const float* __restrict__ Bm, float* __restrict__ C,
    int K, int N, const int* __restrict__ rowmap)
{
    __shared__ float xs[32][33];
    __shared__ float ws[32][257];
    int tid = threadIdx.x;
    int tx = tid & 63, ty = tid >> 6;
    int r0 = blockIdx.x * 32, c0 = blockIdx.y * 256;
    int arl[4];
#pragma unroll
    for (int l = 0; l < 4; l++) {
        int t = (tid + l*256) >> 5;
        arl[l] = rowmap ? rowmap[r0 + t] : (r0 + t);
    }
    float acc[8][4];
#pragma unroll
    for (int r = 0; r < 8; r++)
#pragma unroll
        for (int c = 0; c < 4; c++) acc[r][c] = 0.f;

    for (int k0 = 0; k0 < K; k0 += 32) {
#pragma unroll
        for (int l = 0; l < 4; l++) {
            int idx = tid + l*256; int t = idx >> 5, kk = idx & 31;
            xs[t][kk] = A[(size_t)arl[l]*K + k0 + kk];
        }
#pragma unroll
        for (int l = 0; l < 32; l++) {
            int idx = tid + l*256; int kk = idx >> 8, j = idx & 255;
            ws[kk][j] = Bm[(size_t)(k0 + kk)*N + c0 + j];
        }
        __syncthreads();
#pragma unroll
        for (int kk = 0; kk < 32; kk++) {
            float bw[4], ax[8];
#pragma unroll
            for (int c = 0; c < 4; c++) bw[c] = ws[kk][tx + 64*c];
#pragma unroll
            for (int r = 0; r < 8; r++) ax[r] = xs[ty*8 + r][kk];
#pragma unroll
            for (int r = 0; r < 8; r++)
#pragma unroll
                for (int c = 0; c < 4; c++) acc[r][c] += ax[r]*bw[c];
        }
        __syncthreads();
    }
#pragma unroll
    for (int r = 0; r < 8; r++)
#pragma unroll
        for (int c = 0; c < 4; c++)
            C[(size_t)(r0 + ty*8 + r)*N + c0 + tx + 64*c] = acc[r][c];
}

// =============================================================================
// Kernel 4: serial priority-pool scan. One block per batch, 512 threads.
// Scalar bookkeeping only; row copies deferred (g_src). Warp-cached mins so
// only the touched 32-slot group is re-reduced after each write.
// =============================================================================
__device__ __forceinline__ void warpMinIdx(float &v, int &ix) {
#pragma unroll
    for (int off = 16; off; off >>= 1) {
        float ov = __shfl_down_sync(0xffffffffu, v, off);
        int   oi = __shfl_down_sync(0xffffffffu, ix, off);
        if (ov < v || (ov == v && oi < ix)) { v = ov; ix = oi; }
    }
}

__global__ __launch_bounds__(512) void update_kernel(
    const float* __restrict__ pri_in, const int* __restrict__ counts_in,
    float* __restrict__ out_pri, float* __restrict__ out_cnt)
{
    int b = blockIdx.x, tid = threadIdx.x;
    __shared__ float pri[NP];
    __shared__ float wmin[16];
    __shared__ int   wamin[16];
    __shared__ int   sh_cnt;
    __shared__ float sh_minp;
    __shared__ int   sh_mindx;

    pri[tid] = pri_in[b*NP + tid];
    g_src[b*NP + tid] = -1;
    if (tid == 0) sh_cnt = counts_in[b];
    __syncthreads();
    {
        int lane = tid & 31, w = tid >> 5;
        float v = pri[tid]; int ix = tid;
        warpMinIdx(v, ix);
        if (lane == 0) { wmin[w] = v; wamin[w] = ix; }
    }
    __syncthreads();

    for (int i = 0; i < NP; i++) {
        float imp = g_sscore[b*NT + i];
        bool has = imp > 0.5f;              // TAU1
        if (has) {
            int cnt = sh_cnt;
            if (cnt < NP) {                  // insert phase
                if (tid == 0) {
                    pri[cnt] = imp;
                    g_src[b*NP + cnt] = i;
                    sh_cnt = cnt + 1;
                }
                __syncthreads();
                int w = cnt >> 5;
                if ((tid >> 5) == w) {
                    int lane = tid & 31;
                    float v = pri[w*32 + lane]; int ix = w*32 + lane;
                    warpMinIdx(v, ix);
                    if (lane == 0) { wmin[w] = v; wamin[w] = ix; }
                }
                __syncthreads();
            }
            if (sh_cnt >= NP) {              // replace-min phase (post-insert counts!)
                if (tid < 32) {
                    float v = (tid < 16) ? wmin[tid] : FLT_MAX;
                    int  ix = (tid < 16) ? wamin[tid] : 0x7fffffff;
                    warpMinIdx(v, ix);
                    if (tid == 0) { sh_minp = v; sh_mindx = ix; }
                }
                __syncthreads();
                if (imp > sh_minp) {
                    int mx = sh_mindx;
                    if (tid == 0) { pri[mx] = imp; g_src[b*NP + mx] = i; }
                    __syncthreads();
                    int w = mx >> 5;
                    if ((tid >> 5) == w) {
                        int lane = tid & 31;
                        float v = pri[w*32 + lane]; int ix = w*32 + lane;
                        warpMinIdx(v, ix);
                        if (lane == 0) { wmin[w] = v; wamin[w] = ix; }
                    }
                    __syncthreads();
                }
            }
        }
        __syncthreads();
    }
    if (out_pri) out_pri[b*NP + tid] = pri[tid];
    if (tid == 0) {
        g_counts[b] = sh_cnt;
        if (out_cnt) out_cnt[b] = (float)sh_cnt;
    }
}

// =============================================================================
// Kernel 5: materialize final pool rows (parallel copy per g_src decision)
// =============================================================================
__global__ __launch_bounds__(256) void pool_finalize(
    const float* __restrict__ pool_in, float* __restrict__ out_pool)
{
    int row = blockIdx.x;                 // 0..4095
    int b = row >> 9;
    int s = g_src[row];
    const float* srcrow = (s >= 0) ? (g_summ + (size_t)(b*NP + s)*NS)
                                   : (pool_in + (size_t)row*NS);
    float v = srcrow[threadIdx.x];
    g_poolf[(size_t)row*NS + threadIdx.x] = v;
    if (out_pool) out_pool[(size_t)row*NS + threadIdx.x] = v;
}

// =============================================================================
// Kernel 6: fused attention: logits(q@k^T/16) -> masked softmax -> @v
// One block = 32 tokens of one batch, full 512-slot pool.
// =============================================================================
#define LPITCH 513
__global__ __launch_bounds__(256) void attn_kernel(float* __restrict__ out_retr)
{
    extern __shared__ float sm[];
    float (*xs)[33]     = (float (*)[33])sm;                    // 1056 floats
    float (*ws)[257]    = (float (*)[257])(sm + 1056);          // 8224 floats
    float (*L)[LPITCH]  = (float (*)[LPITCH])(sm + 1056 + 8224);// 32*513 floats

    int tid = threadIdx.x;
    int tx = tid & 63, ty = tid >> 6;
    int b  = blockIdx.x >> 6;
    int t0 = (blockIdx.x & 63) * 32;
    const float* qb = g_q + ((size_t)b*NT + t0)*NS;
    const float* kb = g_k + (size_t)b*NP*NS;
    const float* vb = g_v + (size_t)b*NP*ND;

    // ---- Phase A: logits L[32][512] = qb @ kb^T * (1/16) ----
    for (int p4 = 0; p4 < 2; p4++) {
        float acc[8][4];
#pragma unroll
        for (int r = 0; r < 8; r++)
#pragma unroll
            for (int c = 0; c < 4; c++) acc[r][c] = 0.f;
        for (int k0 = 0; k0 < NS; k0 += 32) {
#pragma unroll
            for (int l = 0; l < 4; l++) {
                int idx = tid + l*256; int t = idx >> 5, kk = idx & 31;
                xs[t][kk] = qb[(size_t)t*NS + k0 + kk];
            }
            {   // transposed load of k rows (coalesced 128B per row)
                int warp = tid >> 5, lane = tid & 31;
#pragma unroll
                for (int rr = 0; rr < 32; rr++) {
                    int pl = warp*32 + rr;
                    ws[lane][pl] = kb[(size_t)(p4*256 + pl)*NS + k0 + lane];
                }
            }
            __syncthreads();
#pragma unroll
            for (int kk = 0; kk < 32; kk++) {
                float bw[4], ax[8];
#pragma unroll
                for (int c = 0; c < 4; c++) bw[c] = ws[kk][tx + 64*c];
#pragma unroll
                for (int r = 0; r < 8; r++) ax[r] = xs[ty*8 + r][kk];
#pragma unroll
                for (int r = 0; r < 8; r++)
#pragma unroll
                    for (int c = 0; c < 4; c++) acc[r][c] += ax[r]*bw[c];
            }
            __syncthreads();
        }
#pragma unroll
        for (int r = 0; r < 8; r++)
#pragma unroll
            for (int c = 0; c < 4; c++)
                L[ty*8 + r][p4*256 + tx + 64*c] = acc[r][c] * 0.0625f;
    }
    __syncthreads();

    // ---- Phase B: masked softmax per row (8 threads/row) ----
    {
        int row = tid >> 3, sub = tid & 7;
        int cnt = g_counts[b];
        float m = -FLT_MAX;
        for (int p = sub; p < cnt; p += 8) m = fmaxf(m, L[row][p]);
#pragma unroll
        for (int off = 4; off; off >>= 1) m = fmaxf(m, __shfl_xor_sync(0xffffffffu, m, off));
        float s = 0.f;
        for (int p = sub; p < cnt; p += 8) {
            float e = expf(L[row][p] - m);
            L[row][p] = e; s += e;
        }
#pragma unroll
        for (int off = 4; off; off >>= 1) s += __shfl_xor_sync(0xffffffffu, s, off);
        float inv = (s > 0.f) ? 1.f/s : 0.f;
        for (int p = sub; p < NP; p += 8) L[row][p] = (p < cnt) ? L[row][p]*inv : 0.f;
    }
    __syncthreads();

    // ---- Phase C: out[32][1024] = L @ vb ----
    for (int cp = 0; cp < 4; cp++) {
        float acc[8][4];
#pragma unroll
        for (int r = 0; r < 8; r++)
#pragma unroll
            for (int c = 0; c < 4; c++) acc[r][c] = 0.f;
        for (int k0 = 0; k0 < NP; k0 += 32) {
#pragma unroll
            for (int l = 0; l < 32; l++) {
                int idx = tid + l*256; int kk = idx >> 8, j = idx & 255;
                ws[kk][j] = vb[(size_t)(k0 + kk)*ND + cp*256 + j];
            }
            __syncthreads();
#pragma unroll
            for (int kk = 0; kk < 32; kk++) {
                float bw[4], ax[8];
#pragma unroll
                for (int c = 0; c < 4; c++) bw[c] = ws[kk][tx + 64*c];
#pragma unroll
                for (int r = 0; r < 8; r++) ax[r] = L[ty*8 + r][k0 + kk];
#pragma unroll
                for (int r = 0; r < 8; r++)
#pragma unroll
                    for (int c = 0; c < 4; c++) acc[r][c] += ax[r]*bw[c];
            }
            __syncthreads();
        }
#pragma unroll
        for (int r = 0; r < 8; r++)
#pragma unroll
            for (int c = 0; c < 4; c++)
                out_retr[((size_t)b*NT + t0 + ty*8 + r)*ND + cp*256 + tx + 64*c] = acc[r][c];
    }
}

// =============================================================================
// launch
// =============================================================================
extern "C" void kernel_launch(void* const* d_in, const int* in_sizes, int n_in,
                              void* d_out, int out_size)
{
    const float* tokens = (const float*)d_in[0];
    const float* pool   = (const float*)d_in[1];
    const float* pri    = (const float*)d_in[2];
    const int*   counts = (const int*)  d_in[3];
    const float* w1     = (const float*)d_in[4];
    const float* w2     = (const float*)d_in[5];
    const float* w_sum  = (const float*)d_in[6];
    const float* wq     = (const float*)d_in[7];
    const float* wk     = (const float*)d_in[8];
    const float* wv     = (const float*)d_in[9];

    float* out = (float*)d_out;
    const int RETR = NB*NT*ND;              // 16777216
    const int POOL = NB*NP*NS;              // 1048576
    const int PRI  = NB*NP;                 // 4096
    float* out_retr = out;
    bool full = (out_size >= RETR + POOL + PRI + NB);
    float* out_pool = full ? out + RETR : nullptr;
    float* out_pri  = full ? out + RETR + POOL : nullptr;
    float* out_cnt  = full ? out + RETR + POOL + PRI : nullptr;

    float *p_summ, *p_poolf, *p_q, *p_k, *p_v;
    int *p_summap;
    cudaGetSymbolAddress((void**)&p_summ,   g_summ);
    cudaGetSymbolAddress((void**)&p_poolf,  g_poolf);
    cudaGetSymbolAddress((void**)&p_q,      g_q);
    cudaGetSymbolAddress((void**)&p_k,      g_k);
    cudaGetSymbolAddress((void**)&p_v,      g_v);
    cudaGetSymbolAddress((void**)&p_summap, g_summap);

    const int ATTN_SMEM = (1056 + 8224 + 32*LPITCH) * 4;
    cudaFuncSetAttribute(attn_kernel, cudaFuncAttributeMaxDynamicSharedMemorySize, ATTN_SMEM);

    // 1. scores (high precision)
    score_kernel<<<(NB*NT)/32, 256>>>(tokens, w1, w2);
    // 2. sort + summary row map
    sort_kernel<<<NB, 1024>>>();
    // 3. summaries = gather(tokens) @ w_sum   [4096,1024]@[1024,256]
    gemm32x256<<<dim3((NB*NP)/32, 1), 256>>>(tokens, w_sum, p_summ, ND, NS, p_summap);
    // 4. serial pool update (scalars only)
    update_kernel<<<NB, NP>>>(pri, counts, out_pri, out_cnt);
    // 5. materialize final pool
    pool_finalize<<<NB*NP, NS>>>(pool, out_pool);
    // 6. q = tokens @ wq   [16384,1024]@[1024,256]
    gemm32x256<<<dim3((NB*NT)/32, 1), 256>>>(tokens, wq, p_q, ND, NS, nullptr);
    // 7. k = pool_final @ wk   [4096,256]@[256,256]
    gemm32x256<<<dim3((NB*NP)/32, 1), 256>>>(p_poolf, wk, p_k, NS, NS, nullptr);
    // 8. v = pool_final @ wv   [4096,256]@[256,1024]
    gemm32x256<<<dim3((NB*NP)/32, 4), 256>>>(p_poolf, wv, p_v, NS, ND, nullptr);
    // 9. fused attention -> retrieved
    attn_kernel<<<NB*(NT/32), 256, ATTN_SMEM>>>(out_retr);
}